// round 1
// baseline (speedup 1.0000x reference)
#include <cuda_runtime.h>
#include <cuda_bf16.h>
#include <math_constants.h>

#define R_MAX 2.0f
#define DR_MIN 0.02f

__global__ void zero_out_kernel(float* out) {
    out[0] = 0.0f;
}

__global__ void __launch_bounds__(256)
exp_repulsion_kernel(const float* __restrict__ dr_vec,
                     const int* __restrict__ Z,
                     const int* __restrict__ idx_i,
                     const int* __restrict__ idx_j,
                     const float* __restrict__ rep_scale,
                     const float* __restrict__ rep_prefactor,
                     float* __restrict__ out,
                     int n_edges)
{
    // cache the 119-entry tables in shared memory (abs applied once)
    __shared__ float s_scale[128];
    __shared__ float s_pref[128];
    if (threadIdx.x < 119) {
        s_scale[threadIdx.x] = fabsf(rep_scale[threadIdx.x]);
        s_pref[threadIdx.x]  = fabsf(rep_prefactor[threadIdx.x]);
    }
    __syncthreads();

    float acc = 0.0f;
    int stride = gridDim.x * blockDim.x;
    for (int e = blockIdx.x * blockDim.x + threadIdx.x; e < n_edges; e += stride) {
        int ii = __ldg(&idx_i[e]);
        int jj = __ldg(&idx_j[e]);
        if (ii == jj) continue;

        float dx = __ldg(&dr_vec[3 * e + 0]);
        float dy = __ldg(&dr_vec[3 * e + 1]);
        float dz = __ldg(&dr_vec[3 * e + 2]);
        float dr = sqrtf(dx * dx + dy * dy + dz * dz);
        dr = fminf(fmaxf(dr, DR_MIN), R_MAX);

        int zi = __ldg(&Z[ii]);
        int zj = __ldg(&Z[jj]);

        float Ri = s_scale[zi];
        float Rj = s_scale[zj];
        float Ai = s_pref[zi];
        float Aj = s_pref[zj];

        float cos_cut = 0.5f * (cospif(dr * (1.0f / R_MAX)) + 1.0f);
        float expo = __expf(-dr * (Ri + Rj) / (Ri * Rj));
        float f = Ai * Aj * expo / (dr * dr);
        acc += f * cos_cut;
    }

    // block reduction
    __shared__ float s_red[256];
    s_red[threadIdx.x] = acc;
    __syncthreads();
    #pragma unroll
    for (int s = 128; s > 32; s >>= 1) {
        if (threadIdx.x < s) s_red[threadIdx.x] += s_red[threadIdx.x + s];
        __syncthreads();
    }
    if (threadIdx.x < 32) {
        float v = s_red[threadIdx.x] + s_red[threadIdx.x + 32];
        #pragma unroll
        for (int off = 16; off > 0; off >>= 1)
            v += __shfl_down_sync(0xFFFFFFFF, v, off);
        if (threadIdx.x == 0)
            atomicAdd(out, v);
    }
}

extern "C" void kernel_launch(void* const* d_in, const int* in_sizes, int n_in,
                              void* d_out, int out_size)
{
    const float* dr_vec        = (const float*)d_in[1];
    const int*   Z             = (const int*)d_in[2];
    const int*   idx           = (const int*)d_in[3];
    const float* rep_scale     = (const float*)d_in[6];
    const float* rep_prefactor = (const float*)d_in[7];
    float* out = (float*)d_out;

    int n_edges = in_sizes[1] / 3;
    const int* idx_i = idx;
    const int* idx_j = idx + n_edges;

    zero_out_kernel<<<1, 1>>>(out);

    int threads = 256;
    int blocks = 1184; // 148 SMs * 8 blocks, grid-stride covers all edges
    exp_repulsion_kernel<<<blocks, threads>>>(dr_vec, Z, idx_i, idx_j,
                                              rep_scale, rep_prefactor,
                                              out, n_edges);
}

// round 2
// speedup vs baseline: 1.4444x; 1.4444x over previous
#include <cuda_runtime.h>
#include <cuda_bf16.h>

#define R_MAX 2.0f
#define DR_MIN 0.02f

// scratch: Z compressed to uint8 (values 0..118). N_ATOMS = 200000 for this problem.
__device__ unsigned char g_Z8[262144];

__global__ void zero_out_kernel(float* out) {
    out[0] = 0.0f;
}

__global__ void z_to_u8_kernel(const int* __restrict__ Z, int n) {
    int i = blockIdx.x * blockDim.x + threadIdx.x;
    if (i < n) g_Z8[i] = (unsigned char)Z[i];
}

__global__ void __launch_bounds__(256)
exp_repulsion_kernel(const float* __restrict__ dr_vec,
                     const int* __restrict__ idx_i,
                     const int* __restrict__ idx_j,
                     const float* __restrict__ rep_scale,
                     const float* __restrict__ rep_prefactor,
                     float* __restrict__ out,
                     int n_edges)
{
    // per-element tables in shared memory: |A| and 1/|R|
    __shared__ float s_pref[128];
    __shared__ float s_invr[128];
    if (threadIdx.x < 119) {
        s_pref[threadIdx.x] = fabsf(rep_prefactor[threadIdx.x]);
        s_invr[threadIdx.x] = 1.0f / fabsf(rep_scale[threadIdx.x]);
    }
    __syncthreads();

    int t = blockIdx.x * blockDim.x + threadIdx.x;
    int e0 = t * 4;
    float acc = 0.0f;

    if (e0 + 3 < n_edges) {
        // fast path: 4 edges, fully vectorized streaming loads (evict-first)
        const float4* dv4 = (const float4*)dr_vec;
        float4 va = __ldcs(dv4 + 3 * t + 0);
        float4 vb = __ldcs(dv4 + 3 * t + 1);
        float4 vc = __ldcs(dv4 + 3 * t + 2);
        int4 ii4 = __ldcs((const int4*)idx_i + t);
        int4 jj4 = __ldcs((const int4*)idx_j + t);

        float ex[4], ey[4], ez[4];
        ex[0] = va.x; ey[0] = va.y; ez[0] = va.z;
        ex[1] = va.w; ey[1] = vb.x; ez[1] = vb.y;
        ex[2] = vb.z; ey[2] = vb.w; ez[2] = vc.x;
        ex[3] = vc.y; ey[3] = vc.z; ez[3] = vc.w;
        int ii[4] = {ii4.x, ii4.y, ii4.z, ii4.w};
        int jj[4] = {jj4.x, jj4.y, jj4.z, jj4.w};

        // issue all gathers up front (L1-cached 200KB table)
        int zi[4], zj[4];
        #pragma unroll
        for (int k = 0; k < 4; k++) {
            zi[k] = (int)g_Z8[ii[k]];
            zj[k] = (int)g_Z8[jj[k]];
        }

        #pragma unroll
        for (int k = 0; k < 4; k++) {
            float dr = sqrtf(ex[k]*ex[k] + ey[k]*ey[k] + ez[k]*ez[k]);
            dr = fminf(fmaxf(dr, DR_MIN), R_MAX);
            float cosc = 0.5f * (cospif(dr * (1.0f / R_MAX)) + 1.0f);
            float Ai = s_pref[zi[k]];
            float Aj = s_pref[zj[k]];
            float bsum = s_invr[zi[k]] + s_invr[zj[k]];
            float f = Ai * Aj * __expf(-dr * bsum) * __fdividef(cosc, dr * dr);
            acc += (ii[k] != jj[k]) ? f : 0.0f;
        }
    } else {
        // tail: scalar, guarded
        for (int k = 0; k < 4; k++) {
            int e = e0 + k;
            if (e >= n_edges) break;
            float dx = __ldcs(&dr_vec[3 * e + 0]);
            float dy = __ldcs(&dr_vec[3 * e + 1]);
            float dz = __ldcs(&dr_vec[3 * e + 2]);
            int ii = __ldcs(&idx_i[e]);
            int jjv = __ldcs(&idx_j[e]);
            int zi = (int)g_Z8[ii];
            int zj = (int)g_Z8[jjv];
            float dr = sqrtf(dx*dx + dy*dy + dz*dz);
            dr = fminf(fmaxf(dr, DR_MIN), R_MAX);
            float cosc = 0.5f * (cospif(dr * (1.0f / R_MAX)) + 1.0f);
            float f = s_pref[zi] * s_pref[zj] *
                      __expf(-dr * (s_invr[zi] + s_invr[zj])) *
                      __fdividef(cosc, dr * dr);
            acc += (ii != jjv) ? f : 0.0f;
        }
    }

    // warp reduce, then block reduce via smem, one atomic per block
    #pragma unroll
    for (int off = 16; off > 0; off >>= 1)
        acc += __shfl_down_sync(0xFFFFFFFF, acc, off);

    __shared__ float s_part[8];
    int warp = threadIdx.x >> 5;
    if ((threadIdx.x & 31) == 0) s_part[warp] = acc;
    __syncthreads();
    if (threadIdx.x < 8) {
        float v = s_part[threadIdx.x];
        #pragma unroll
        for (int off = 4; off > 0; off >>= 1)
            v += __shfl_down_sync(0xFF, v, off);
        if (threadIdx.x == 0)
            atomicAdd(out, v);
    }
}

extern "C" void kernel_launch(void* const* d_in, const int* in_sizes, int n_in,
                              void* d_out, int out_size)
{
    const float* dr_vec        = (const float*)d_in[1];
    const int*   Z             = (const int*)d_in[2];
    const int*   idx           = (const int*)d_in[3];
    const float* rep_scale     = (const float*)d_in[6];
    const float* rep_prefactor = (const float*)d_in[7];
    float* out = (float*)d_out;

    int n_edges = in_sizes[1] / 3;
    int n_atoms = in_sizes[2];
    const int* idx_i = idx;
    const int* idx_j = idx + n_edges;

    zero_out_kernel<<<1, 1>>>(out);
    z_to_u8_kernel<<<(n_atoms + 255) / 256, 256>>>(Z, n_atoms);

    int n_thr = (n_edges + 3) / 4;
    int blocks = (n_thr + 255) / 256;
    exp_repulsion_kernel<<<blocks, 256>>>(dr_vec, idx_i, idx_j,
                                          rep_scale, rep_prefactor,
                                          out, n_edges);
}

// round 3
// speedup vs baseline: 1.4801x; 1.0247x over previous
#include <cuda_runtime.h>
#include <cuda_bf16.h>

#define R_MAX 2.0f
#define DR_MIN 0.02f
#define NBLOCKS 148
#define NTHREADS 1024

__device__ float g_partials[NBLOCKS];
__device__ unsigned int g_count = 0;

__global__ void __launch_bounds__(NTHREADS, 1)
exp_rep_kernel(const float* __restrict__ dr_vec,
               const int* __restrict__ Z,
               const int* __restrict__ idx_i,
               const int* __restrict__ idx_j,
               const float* __restrict__ rep_scale,
               const float* __restrict__ rep_prefactor,
               float* __restrict__ out,
               int n_edges, int n_atoms)
{
    extern __shared__ unsigned char smem[];
    float2* s_tab = (float2*)smem;              // 119 x {|A|, 1/|R|}, padded to 1024B
    unsigned char* s_Z = smem + 1024;           // n_atoms bytes (uint8 Z)

    int tid = threadIdx.x;
    if (tid < 119) {
        s_tab[tid] = make_float2(fabsf(rep_prefactor[tid]),
                                 1.0f / fabsf(rep_scale[tid]));
    }
    // stage Z (int32) -> smem uint8, vectorized
    int n4 = n_atoms >> 2;
    const int4* Z4 = (const int4*)Z;
    uchar4* sZ4 = (uchar4*)s_Z;
    for (int i = tid; i < n4; i += NTHREADS) {
        int4 z = __ldg(Z4 + i);
        sZ4[i] = make_uchar4((unsigned char)z.x, (unsigned char)z.y,
                             (unsigned char)z.z, (unsigned char)z.w);
    }
    for (int i = (n4 << 2) + tid; i < n_atoms; i += NTHREADS)
        s_Z[i] = (unsigned char)Z[i];
    __syncthreads();

    float acc = 0.0f;
    int n_chunks = n_edges >> 2;
    int gstride = NBLOCKS * NTHREADS;
    const float4* dv4 = (const float4*)dr_vec;
    const int4*   I4  = (const int4*)idx_i;
    const int4*   J4  = (const int4*)idx_j;

    for (int c = blockIdx.x * NTHREADS + tid; c < n_chunks; c += gstride) {
        float4 va = __ldcs(dv4 + 3 * c + 0);
        float4 vb = __ldcs(dv4 + 3 * c + 1);
        float4 vc = __ldcs(dv4 + 3 * c + 2);
        int4 ii4 = __ldcs(I4 + c);
        int4 jj4 = __ldcs(J4 + c);

        float ex[4], ey[4], ez[4];
        ex[0] = va.x; ey[0] = va.y; ez[0] = va.z;
        ex[1] = va.w; ey[1] = vb.x; ez[1] = vb.y;
        ex[2] = vb.z; ey[2] = vb.w; ez[2] = vc.x;
        ex[3] = vc.y; ey[3] = vc.z; ez[3] = vc.w;
        int ii[4] = {ii4.x, ii4.y, ii4.z, ii4.w};
        int jj[4] = {jj4.x, jj4.y, jj4.z, jj4.w};

        // smem gathers up front (independent -> overlap LDS latency)
        int zi[4], zj[4];
        #pragma unroll
        for (int k = 0; k < 4; k++) {
            zi[k] = (int)s_Z[ii[k]];
            zj[k] = (int)s_Z[jj[k]];
        }
        float2 pi[4], pj[4];
        #pragma unroll
        for (int k = 0; k < 4; k++) {
            pi[k] = s_tab[zi[k]];
            pj[k] = s_tab[zj[k]];
        }

        #pragma unroll
        for (int k = 0; k < 4; k++) {
            float dr = sqrtf(ex[k]*ex[k] + ey[k]*ey[k] + ez[k]*ez[k]);
            dr = fminf(fmaxf(dr, DR_MIN), R_MAX);
            float cosc = 0.5f * (cospif(dr * (1.0f / R_MAX)) + 1.0f);
            float f = pi[k].x * pj[k].x * __expf(-dr * (pi[k].y + pj[k].y)) *
                      __fdividef(cosc, dr * dr);
            acc += (ii[k] != jj[k]) ? f : 0.0f;
        }
    }

    // remainder edges (n_edges % 4) handled by block 0, thread 0
    if (blockIdx.x == 0 && tid == 0) {
        for (int e = n_chunks << 2; e < n_edges; e++) {
            float dx = dr_vec[3*e+0], dy = dr_vec[3*e+1], dz = dr_vec[3*e+2];
            int ii = idx_i[e], jj = idx_j[e];
            float2 pi = s_tab[(int)s_Z[ii]];
            float2 pj = s_tab[(int)s_Z[jj]];
            float dr = sqrtf(dx*dx + dy*dy + dz*dz);
            dr = fminf(fmaxf(dr, DR_MIN), R_MAX);
            float cosc = 0.5f * (cospif(dr * (1.0f / R_MAX)) + 1.0f);
            float f = pi.x * pj.x * __expf(-dr * (pi.y + pj.y)) *
                      __fdividef(cosc, dr * dr);
            acc += (ii != jj) ? f : 0.0f;
        }
    }

    // warp reduce
    #pragma unroll
    for (int off = 16; off > 0; off >>= 1)
        acc += __shfl_down_sync(0xFFFFFFFF, acc, off);

    __shared__ float s_red[32];
    int warp = tid >> 5;
    if ((tid & 31) == 0) s_red[warp] = acc;
    __syncthreads();
    if (warp == 0) {
        float v = (tid < (NTHREADS / 32)) ? s_red[tid] : 0.0f;
        #pragma unroll
        for (int off = 16; off > 0; off >>= 1)
            v += __shfl_down_sync(0xFFFFFFFF, v, off);
        if (tid == 0) {
            g_partials[blockIdx.x] = v;
            __threadfence();
            unsigned int ticket = atomicAdd(&g_count, 1u);
            if (ticket == NBLOCKS - 1) {
                // deterministic fixed-order final sum
                float s = 0.0f;
                #pragma unroll 4
                for (int i = 0; i < NBLOCKS; i++) s += g_partials[i];
                out[0] = s;
                g_count = 0;  // reset for next launch
            }
        }
    }
}

extern "C" void kernel_launch(void* const* d_in, const int* in_sizes, int n_in,
                              void* d_out, int out_size)
{
    const float* dr_vec        = (const float*)d_in[1];
    const int*   Z             = (const int*)d_in[2];
    const int*   idx           = (const int*)d_in[3];
    const float* rep_scale     = (const float*)d_in[6];
    const float* rep_prefactor = (const float*)d_in[7];
    float* out = (float*)d_out;

    int n_edges = in_sizes[1] / 3;
    int n_atoms = in_sizes[2];
    const int* idx_i = idx;
    const int* idx_j = idx + n_edges;

    int smem_bytes = 1024 + ((n_atoms + 127) & ~127);
    cudaFuncSetAttribute(exp_rep_kernel,
                         cudaFuncAttributeMaxDynamicSharedMemorySize, smem_bytes);

    exp_rep_kernel<<<NBLOCKS, NTHREADS, smem_bytes>>>(
        dr_vec, Z, idx_i, idx_j, rep_scale, rep_prefactor,
        out, n_edges, n_atoms);
}

// round 4
// speedup vs baseline: 1.7193x; 1.1616x over previous
#include <cuda_runtime.h>
#include <cuda_bf16.h>

#define R_MAX 2.0f
#define DR_MIN 0.02f
#define NBLOCKS 148
#define NTHREADS 768

__device__ float g_partials[NBLOCKS];
__device__ unsigned int g_count = 0;

__global__ void __launch_bounds__(NTHREADS, 1)
exp_rep_kernel(const float* __restrict__ dr_vec,
               const int* __restrict__ Z,
               const int* __restrict__ idx_i,
               const int* __restrict__ idx_j,
               const float* __restrict__ rep_scale,
               const float* __restrict__ rep_prefactor,
               float* __restrict__ out,
               int n_edges, int n_atoms)
{
    extern __shared__ unsigned char smem[];
    float2* s_tab = (float2*)smem;              // 119 x {|A|, 1/|R|}
    unsigned char* s_Z = smem + 1024;           // n_atoms bytes (uint8 Z)

    int tid = threadIdx.x;
    if (tid < 119) {
        s_tab[tid] = make_float2(fabsf(rep_prefactor[tid]),
                                 1.0f / fabsf(rep_scale[tid]));
    }
    // stage Z (int32) -> smem uint8, vectorized
    int n4a = n_atoms >> 2;
    const int4* Z4 = (const int4*)Z;
    uchar4* sZ4 = (uchar4*)s_Z;
    for (int i = tid; i < n4a; i += NTHREADS) {
        int4 z = __ldg(Z4 + i);
        sZ4[i] = make_uchar4((unsigned char)z.x, (unsigned char)z.y,
                             (unsigned char)z.z, (unsigned char)z.w);
    }
    for (int i = (n4a << 2) + tid; i < n_atoms; i += NTHREADS)
        s_Z[i] = (unsigned char)Z[i];
    __syncthreads();

    float acc = 0.0f;
    int n_chunks = n_edges >> 2;
    int gstride = NBLOCKS * NTHREADS;
    const float4* dv4 = (const float4*)dr_vec;
    const int4*   I4  = (const int4*)idx_i;
    const int4*   J4  = (const int4*)idx_j;

    // ---- software pipeline: prefetch depth 1 ----
    int c = blockIdx.x * NTHREADS + tid;
    bool valid = (c < n_chunks);
    float4 va, vb, vc;
    int4 ii4, jj4;
    va = vb = vc = make_float4(0.f, 0.f, 0.f, 0.f);
    ii4 = jj4 = make_int4(0, 0, 0, 0);
    if (valid) {
        ii4 = __ldcs(I4 + c);
        jj4 = __ldcs(J4 + c);
        va  = __ldcs(dv4 + 3 * c + 0);
        vb  = __ldcs(dv4 + 3 * c + 1);
        vc  = __ldcs(dv4 + 3 * c + 2);
    }

    while (valid) {
        int cn = c + gstride;
        bool nvalid = (cn < n_chunks);
        float4 nva = va, nvb = vb, nvc = vc;
        int4 nii = ii4, njj = jj4;
        if (nvalid) {
            nii = __ldcs(I4 + cn);
            njj = __ldcs(J4 + cn);
            nva = __ldcs(dv4 + 3 * cn + 0);
            nvb = __ldcs(dv4 + 3 * cn + 1);
            nvc = __ldcs(dv4 + 3 * cn + 2);
        }

        // ---- compute current chunk (idx arrived ~1 iteration ago) ----
        float ex[4], ey[4], ez[4];
        ex[0] = va.x; ey[0] = va.y; ez[0] = va.z;
        ex[1] = va.w; ey[1] = vb.x; ez[1] = vb.y;
        ex[2] = vb.z; ey[2] = vb.w; ez[2] = vc.x;
        ex[3] = vc.y; ey[3] = vc.z; ez[3] = vc.w;
        int ii[4] = {ii4.x, ii4.y, ii4.z, ii4.w};
        int jj[4] = {jj4.x, jj4.y, jj4.z, jj4.w};

        int zi[4], zj[4];
        #pragma unroll
        for (int k = 0; k < 4; k++) {
            zi[k] = (int)s_Z[ii[k]];
            zj[k] = (int)s_Z[jj[k]];
        }
        float2 pi[4], pj[4];
        #pragma unroll
        for (int k = 0; k < 4; k++) {
            pi[k] = s_tab[zi[k]];
            pj[k] = s_tab[zj[k]];
        }

        #pragma unroll
        for (int k = 0; k < 4; k++) {
            float dr = sqrtf(ex[k]*ex[k] + ey[k]*ey[k] + ez[k]*ez[k]);
            dr = fminf(fmaxf(dr, DR_MIN), R_MAX);
            float cosc = 0.5f * (cospif(dr * (1.0f / R_MAX)) + 1.0f);
            float f = pi[k].x * pj[k].x * __expf(-dr * (pi[k].y + pj[k].y)) *
                      __fdividef(cosc, dr * dr);
            acc += (ii[k] != jj[k]) ? f : 0.0f;
        }

        // rotate pipeline
        c = cn; valid = nvalid;
        va = nva; vb = nvb; vc = nvc;
        ii4 = nii; jj4 = njj;
    }

    // remainder edges (n_edges % 4): block 0, thread 0
    if (blockIdx.x == 0 && tid == 0) {
        for (int e = n_chunks << 2; e < n_edges; e++) {
            float dx = dr_vec[3*e+0], dy = dr_vec[3*e+1], dz = dr_vec[3*e+2];
            int ii = idx_i[e], jj = idx_j[e];
            float2 pi = s_tab[(int)s_Z[ii]];
            float2 pj = s_tab[(int)s_Z[jj]];
            float dr = sqrtf(dx*dx + dy*dy + dz*dz);
            dr = fminf(fmaxf(dr, DR_MIN), R_MAX);
            float cosc = 0.5f * (cospif(dr * (1.0f / R_MAX)) + 1.0f);
            float f = pi.x * pj.x * __expf(-dr * (pi.y + pj.y)) *
                      __fdividef(cosc, dr * dr);
            acc += (ii != jj) ? f : 0.0f;
        }
    }

    // warp reduce, block reduce, deterministic cross-block finish
    #pragma unroll
    for (int off = 16; off > 0; off >>= 1)
        acc += __shfl_down_sync(0xFFFFFFFF, acc, off);

    __shared__ float s_red[32];
    int warp = tid >> 5;
    if ((tid & 31) == 0) s_red[warp] = acc;
    __syncthreads();
    if (warp == 0) {
        float v = (tid < (NTHREADS / 32)) ? s_red[tid] : 0.0f;
        #pragma unroll
        for (int off = 16; off > 0; off >>= 1)
            v += __shfl_down_sync(0xFFFFFFFF, v, off);
        if (tid == 0) {
            g_partials[blockIdx.x] = v;
            __threadfence();
            unsigned int ticket = atomicAdd(&g_count, 1u);
            if (ticket == NBLOCKS - 1) {
                float s = 0.0f;
                #pragma unroll 4
                for (int i = 0; i < NBLOCKS; i++) s += g_partials[i];
                out[0] = s;
                g_count = 0;  // reset for next graph replay
            }
        }
    }
}

extern "C" void kernel_launch(void* const* d_in, const int* in_sizes, int n_in,
                              void* d_out, int out_size)
{
    const float* dr_vec        = (const float*)d_in[1];
    const int*   Z             = (const int*)d_in[2];
    const int*   idx           = (const int*)d_in[3];
    const float* rep_scale     = (const float*)d_in[6];
    const float* rep_prefactor = (const float*)d_in[7];
    float* out = (float*)d_out;

    int n_edges = in_sizes[1] / 3;
    int n_atoms = in_sizes[2];
    const int* idx_i = idx;
    const int* idx_j = idx + n_edges;

    int smem_bytes = 1024 + ((n_atoms + 127) & ~127);
    cudaFuncSetAttribute(exp_rep_kernel,
                         cudaFuncAttributeMaxDynamicSharedMemorySize, smem_bytes);

    exp_rep_kernel<<<NBLOCKS, NTHREADS, smem_bytes>>>(
        dr_vec, Z, idx_i, idx_j, rep_scale, rep_prefactor,
        out, n_edges, n_atoms);
}